// round 1
// baseline (speedup 1.0000x reference)
#include <cuda_runtime.h>

#define HIDDEN 768
#define FF     3072
#define NSEQ   128
#define TOKENS 65536
#define TOKB   32

// ---------------- scratch (device globals: no allocation) ----------------
__device__ float g_sums[NSEQ * HIDDEN];   // segment sums
__device__ float g_invlen[NSEQ];          // 1/len per segment
__device__ float g_h1[NSEQ * FF];         // after dense1
__device__ float g_h2[NSEQ * HIDDEN];     // after dense2 (atomic split-K target)

// ---------------- zero / invlen ----------------
__global__ void zero_kernel(const int* __restrict__ lens) {
    int i = blockIdx.x * blockDim.x + threadIdx.x;
    if (i < NSEQ * HIDDEN) {
        g_sums[i] = 0.0f;
        g_h2[i]   = 0.0f;
    }
    if (i < NSEQ) {
        g_invlen[i] = 1.0f / (float)lens[i];
    }
}

// ---------------- segment sum pooling ----------------
// grid = TOKENS/TOKB blocks, 192 threads (one float4 column group per thread)
__global__ __launch_bounds__(192) void pool_kernel(const float* __restrict__ hs,
                                                   const int* __restrict__ lens) {
    __shared__ int sl[NSEQ];      // inclusive cumsum of lens
    __shared__ int segof[TOKB];

    int tid = threadIdx.x;
    if (tid < NSEQ) sl[tid] = lens[tid];
    __syncthreads();
    // Hillis-Steele inclusive scan over 128 entries
    #pragma unroll
    for (int off = 1; off < NSEQ; off <<= 1) {
        int v = 0;
        if (tid < NSEQ && tid >= off) v = sl[tid - off];
        __syncthreads();
        if (tid < NSEQ) sl[tid] += v;
        __syncthreads();
    }

    int t0 = blockIdx.x * TOKB;
    if (tid < TOKB) {
        int t = t0 + tid;
        int lo = 0, hi = NSEQ - 1;
        while (lo < hi) {                 // first s with cum[s] > t
            int mid = (lo + hi) >> 1;
            if (sl[mid] > t) hi = mid; else lo = mid + 1;
        }
        segof[tid] = lo;
    }
    __syncthreads();

    const float4* h4 = (const float4*)hs;
    int col = tid;                        // 0..191 float4 columns
    float4 acc = make_float4(0.f, 0.f, 0.f, 0.f);
    int cur = segof[0];

    #pragma unroll
    for (int i = 0; i < TOKB; i++) {
        float4 v = h4[(size_t)(t0 + i) * (HIDDEN / 4) + col];
        int s = segof[i];
        if (s != cur) {
            float* dst = &g_sums[cur * HIDDEN + col * 4];
            atomicAdd(dst + 0, acc.x); atomicAdd(dst + 1, acc.y);
            atomicAdd(dst + 2, acc.z); atomicAdd(dst + 3, acc.w);
            acc = make_float4(0.f, 0.f, 0.f, 0.f);
            cur = s;
        }
        acc.x += v.x; acc.y += v.y; acc.z += v.z; acc.w += v.w;
    }
    {
        float* dst = &g_sums[cur * HIDDEN + col * 4];
        atomicAdd(dst + 0, acc.x); atomicAdd(dst + 1, acc.y);
        atomicAdd(dst + 2, acc.z); atomicAdd(dst + 3, acc.w);
    }
}

// ---------------- packed f32x2 FMA ----------------
union U64 {
    float2 f2;
    unsigned long long u;
};

__device__ __forceinline__ void ffma2(U64& d, U64 a, U64 b) {
    asm("fma.rn.f32x2 %0, %1, %2, %0;" : "+l"(d.u) : "l"(a.u), "l"(b.u));
}

// ---------------- generic NT GEMM tile: C[BM=64, BN=32] over BK=32 chunks ----------------
// A: [M, ldA] row-major (K contiguous). B: [N, ldB] row-major (K contiguous).
// 256 threads as 16x16, micro-tile 4x2, f32x2 packed along K.
__device__ __forceinline__ void gemm_tile(
    const float* __restrict__ A, const float* __restrict__ B, float* __restrict__ C,
    int ldA, int ldB, int ldC,
    int m0, int n0, int k0, int kIters,
    const float* __restrict__ rowScaleA, bool atomic)
{
    __shared__ float2 As[16][65];   // [k2][m], padded
    __shared__ float2 Bs[16][33];   // [k2][n], padded

    int tid = threadIdx.x;
    int tx = tid & 15, ty = tid >> 4;

    U64 c[4][2];
    #pragma unroll
    for (int i = 0; i < 4; i++)
        #pragma unroll
        for (int j = 0; j < 2; j++) c[i][j].f2 = make_float2(0.f, 0.f);

    // per-row scale for the two A rows this thread loads (constant over k-loop)
    float sA0 = 1.0f, sA1 = 1.0f;
    int rowA0 = (tid)       >> 3;
    int rowA1 = (tid + 256) >> 3;
    if (rowScaleA) { sA0 = rowScaleA[m0 + rowA0]; sA1 = rowScaleA[m0 + rowA1]; }

    for (int kt = 0; kt < kIters; kt++) {
        int kk = k0 + kt * 32;

        // load A tile: 64 rows x 32 k-floats = 512 float4, 2 per thread
        {
            int q0 = tid & 7;
            float4 v = *(const float4*)(A + (size_t)(m0 + rowA0) * ldA + kk + q0 * 4);
            v.x *= sA0; v.y *= sA0; v.z *= sA0; v.w *= sA0;
            As[q0 * 2 + 0][rowA0] = make_float2(v.x, v.y);
            As[q0 * 2 + 1][rowA0] = make_float2(v.z, v.w);

            int q1 = (tid + 256) & 7;
            float4 w = *(const float4*)(A + (size_t)(m0 + rowA1) * ldA + kk + q1 * 4);
            w.x *= sA1; w.y *= sA1; w.z *= sA1; w.w *= sA1;
            As[q1 * 2 + 0][rowA1] = make_float2(w.x, w.y);
            As[q1 * 2 + 1][rowA1] = make_float2(w.z, w.w);
        }
        // load B tile: 32 rows x 32 k-floats = 256 float4, 1 per thread
        {
            int row = tid >> 3, q = tid & 7;
            float4 v = *(const float4*)(B + (size_t)(n0 + row) * ldB + kk + q * 4);
            Bs[q * 2 + 0][row] = make_float2(v.x, v.y);
            Bs[q * 2 + 1][row] = make_float2(v.z, v.w);
        }
        __syncthreads();

        #pragma unroll
        for (int k2 = 0; k2 < 16; k2++) {
            U64 a[4], b[2];
            #pragma unroll
            for (int i = 0; i < 4; i++) a[i].f2 = As[k2][ty * 4 + i];
            #pragma unroll
            for (int j = 0; j < 2; j++) b[j].f2 = Bs[k2][tx * 2 + j];
            #pragma unroll
            for (int i = 0; i < 4; i++)
                #pragma unroll
                for (int j = 0; j < 2; j++)
                    ffma2(c[i][j], a[i], b[j]);
        }
        __syncthreads();
    }

    #pragma unroll
    for (int i = 0; i < 4; i++) {
        int rg = m0 + ty * 4 + i;
        #pragma unroll
        for (int j = 0; j < 2; j++) {
            int cg = n0 + tx * 2 + j;
            float val = c[i][j].f2.x + c[i][j].f2.y;
            if (atomic) atomicAdd(&C[(size_t)rg * ldC + cg], val);
            else        C[(size_t)rg * ldC + cg] = val;
        }
    }
}

// GEMM1: h1[128,3072] = (sums * invlen) @ W1^T ; W1 [3072,768] row-major
// grid (FF/32 = 96, 128/64 = 2)
__global__ __launch_bounds__(256) void gemm1_kernel(const float* __restrict__ W1) {
    gemm_tile(g_sums, W1, g_h1,
              HIDDEN, HIDDEN, FF,
              blockIdx.y * 64, blockIdx.x * 32, 0, HIDDEN / 32,
              g_invlen, false);
}

// GEMM2: h2[128,768] += h1 @ W2^T ; W2 [768,3072] row-major; split-K = 4
// grid (768/32 = 24, 128/64 = 2, 4)
__global__ __launch_bounds__(256) void gemm2_kernel(const float* __restrict__ W2) {
    gemm_tile(g_h1, W2, g_h2,
              FF, FF, HIDDEN,
              blockIdx.y * 64, blockIdx.x * 32, blockIdx.z * (FF / 4), (FF / 4) / 32,
              nullptr, true);
}

// ---------------- L2 normalize rows ----------------
__global__ __launch_bounds__(256) void norm_kernel(float* __restrict__ out) {
    int s = blockIdx.x, tid = threadIdx.x;
    const float* row = &g_h2[s * HIDDEN];
    float ss = 0.f;
    for (int i = tid; i < HIDDEN; i += 256) { float v = row[i]; ss += v * v; }

    __shared__ float red[8];
    #pragma unroll
    for (int o = 16; o > 0; o >>= 1) ss += __shfl_xor_sync(0xffffffffu, ss, o);
    if ((tid & 31) == 0) red[tid >> 5] = ss;
    __syncthreads();
    __shared__ float sInv;
    if (tid == 0) {
        float tot = 0.f;
        #pragma unroll
        for (int w = 0; w < 8; w++) tot += red[w];
        sInv = 1.0f / fmaxf(sqrtf(tot), 1e-12f);
    }
    __syncthreads();
    float inv = sInv;
    for (int i = tid; i < HIDDEN; i += 256) out[s * HIDDEN + i] = row[i] * inv;
}

// ---------------- launch ----------------
extern "C" void kernel_launch(void* const* d_in, const int* in_sizes, int n_in,
                              void* d_out, int out_size) {
    const float* hs   = (const float*)d_in[0];   // [65536, 768] fp32
    const int*   lens = (const int*)  d_in[1];   // [128] int32
    const float* W1   = (const float*)d_in[2];   // [3072, 768] fp32
    const float* W2   = (const float*)d_in[3];   // [768, 3072] fp32
    float* out = (float*)d_out;                  // [128, 768] fp32

    zero_kernel<<<(NSEQ * HIDDEN + 255) / 256, 256>>>(lens);
    pool_kernel<<<TOKENS / TOKB, 192>>>(hs, lens);
    gemm1_kernel<<<dim3(FF / 32, NSEQ / 64), 256>>>(W1);
    gemm2_kernel<<<dim3(HIDDEN / 32, NSEQ / 64, 4), 256>>>(W2);
    norm_kernel<<<NSEQ, 256>>>(out);
}

// round 2
// speedup vs baseline: 1.2368x; 1.2368x over previous
#include <cuda_runtime.h>

#define HIDDEN 768
#define FF     3072
#define NSEQ   128
#define TOKENS 65536
#define TOKB   32
#define SPLIT1 4      // gemm1 K-split (separate partial buffers)
#define SPLIT2 16     // gemm2 K-split (atomic epilogue)

// ---------------- scratch (device globals: no allocation) ----------------
__device__ float g_sums[NSEQ * HIDDEN];            // segment sums
__device__ float g_invlen[NSEQ];                   // 1/len
__device__ float g_h1p[SPLIT1 * NSEQ * FF];        // gemm1 partials (no zero needed)
__device__ float g_h2[NSEQ * HIDDEN];              // gemm2 atomic target

// ---------------- zero / invlen ----------------
__global__ void zero_kernel(const int* __restrict__ lens) {
    int i = blockIdx.x * blockDim.x + threadIdx.x;
    if (i < NSEQ * HIDDEN) {
        g_sums[i] = 0.0f;
        g_h2[i]   = 0.0f;
    }
    if (i < NSEQ) g_invlen[i] = 1.0f / (float)lens[i];
}

// ---------------- segment sum pooling ----------------
__global__ __launch_bounds__(192) void pool_kernel(const float* __restrict__ hs,
                                                   const int* __restrict__ lens) {
    __shared__ int sl[NSEQ];
    __shared__ int segof[TOKB];

    int tid = threadIdx.x;
    if (tid < NSEQ) sl[tid] = lens[tid];
    __syncthreads();
    #pragma unroll
    for (int off = 1; off < NSEQ; off <<= 1) {
        int v = 0;
        if (tid < NSEQ && tid >= off) v = sl[tid - off];
        __syncthreads();
        if (tid < NSEQ) sl[tid] += v;
        __syncthreads();
    }

    int t0 = blockIdx.x * TOKB;
    if (tid < TOKB) {
        int t = t0 + tid;
        int lo = 0, hi = NSEQ - 1;
        while (lo < hi) {
            int mid = (lo + hi) >> 1;
            if (sl[mid] > t) hi = mid; else lo = mid + 1;
        }
        segof[tid] = lo;
    }
    __syncthreads();

    const float4* h4 = (const float4*)hs;
    int col = tid;
    float4 acc = make_float4(0.f, 0.f, 0.f, 0.f);
    int cur = segof[0];

    #pragma unroll
    for (int i = 0; i < TOKB; i++) {
        float4 v = h4[(size_t)(t0 + i) * (HIDDEN / 4) + col];
        int s = segof[i];
        if (s != cur) {
            float* dst = &g_sums[cur * HIDDEN + col * 4];
            atomicAdd(dst + 0, acc.x); atomicAdd(dst + 1, acc.y);
            atomicAdd(dst + 2, acc.z); atomicAdd(dst + 3, acc.w);
            acc = make_float4(0.f, 0.f, 0.f, 0.f);
            cur = s;
        }
        acc.x += v.x; acc.y += v.y; acc.z += v.z; acc.w += v.w;
    }
    {
        float* dst = &g_sums[cur * HIDDEN + col * 4];
        atomicAdd(dst + 0, acc.x); atomicAdd(dst + 1, acc.y);
        atomicAdd(dst + 2, acc.z); atomicAdd(dst + 3, acc.w);
    }
}

// ---------------- packed f32x2 FMA ----------------
union U64 {
    float2 f2;
    unsigned long long u;
};

__device__ __forceinline__ void ffma2(U64& d, U64 a, U64 b) {
    asm("fma.rn.f32x2 %0, %1, %2, %0;" : "+l"(d.u) : "l"(a.u), "l"(b.u));
}

template<int NSUM>
__device__ __forceinline__ float4 ld_sum(const float* __restrict__ p, size_t stride) {
    float4 v = *(const float4*)p;
    #pragma unroll
    for (int i = 1; i < NSUM; i++) {
        float4 w = *(const float4*)(p + (size_t)i * stride);
        v.x += w.x; v.y += w.y; v.z += w.z; v.w += w.w;
    }
    return v;
}

// ---- double-buffered NT GEMM core: C[64,32] tile, BK=32, one sync/iter ----
// A: [M, ldA] K-contiguous (optionally sum of NSUM partial buffers, stride apart)
// B: [N, ldB] K-contiguous.
template<int NSUM>
__device__ __forceinline__ void gemm_core(
    const float* __restrict__ A, const float* __restrict__ B,
    int ldA, int ldB, int m0, int n0, int k0, int kIters,
    size_t aStride, U64 (&c)[4][2])
{
    __shared__ float2 As[2][16][65];
    __shared__ float2 Bs[2][16][33];

    int tid = threadIdx.x;
    int q   = tid & 7;          // float4 index within 32-float K chunk
    int row = tid >> 3;         // 0..31

    const float* pa0 = A + (size_t)(m0 + row) * ldA + k0 + q * 4;
    const float* pa1 = pa0 + (size_t)32 * ldA;
    const float* pb  = B + (size_t)(n0 + row) * ldB + k0 + q * 4;

    float4 va0 = ld_sum<NSUM>(pa0, aStride);
    float4 va1 = ld_sum<NSUM>(pa1, aStride);
    float4 vb  = *(const float4*)pb;

    int tx = tid & 15, ty = tid >> 4;

    for (int kt = 0; kt < kIters; kt++) {
        int buf = kt & 1;
        As[buf][q * 2 + 0][row]      = make_float2(va0.x, va0.y);
        As[buf][q * 2 + 1][row]      = make_float2(va0.z, va0.w);
        As[buf][q * 2 + 0][row + 32] = make_float2(va1.x, va1.y);
        As[buf][q * 2 + 1][row + 32] = make_float2(va1.z, va1.w);
        Bs[buf][q * 2 + 0][row]      = make_float2(vb.x, vb.y);
        Bs[buf][q * 2 + 1][row]      = make_float2(vb.z, vb.w);
        __syncthreads();

        if (kt + 1 < kIters) {
            int off = (kt + 1) * 32;
            va0 = ld_sum<NSUM>(pa0 + off, aStride);
            va1 = ld_sum<NSUM>(pa1 + off, aStride);
            vb  = *(const float4*)(pb + off);
        }

        #pragma unroll
        for (int k2 = 0; k2 < 16; k2++) {
            U64 a[4], b[2];
            #pragma unroll
            for (int i = 0; i < 4; i++) a[i].f2 = As[buf][k2][ty * 4 + i];
            #pragma unroll
            for (int j = 0; j < 2; j++) b[j].f2 = Bs[buf][k2][tx * 2 + j];
            #pragma unroll
            for (int i = 0; i < 4; i++)
                #pragma unroll
                for (int j = 0; j < 2; j++)
                    ffma2(c[i][j], a[i], b[j]);
        }
        // no second sync: double buffer guarantees safety with one barrier/iter
    }
}

// GEMM1: h1p[kz] = (sums @ W1^T) * invlen, K chunk = 768/4 = 192
// grid (FF/32=96, 128/64=2, SPLIT1=4)
__global__ __launch_bounds__(256, 4) void gemm1_kernel(const float* __restrict__ W1) {
    U64 c[4][2];
    #pragma unroll
    for (int i = 0; i < 4; i++)
        #pragma unroll
        for (int j = 0; j < 2; j++) c[i][j].f2 = make_float2(0.f, 0.f);

    int m0 = blockIdx.y * 64, n0 = blockIdx.x * 32, kz = blockIdx.z;
    gemm_core<1>(g_sums, W1, HIDDEN, HIDDEN, m0, n0, kz * (HIDDEN / SPLIT1),
                 (HIDDEN / SPLIT1) / 32, 0, c);

    float* C = g_h1p + (size_t)kz * NSEQ * FF;
    int tx = threadIdx.x & 15, ty = threadIdx.x >> 4;
    #pragma unroll
    for (int i = 0; i < 4; i++) {
        int rg = m0 + ty * 4 + i;
        float s = g_invlen[rg];
        #pragma unroll
        for (int j = 0; j < 2; j++) {
            int cg = n0 + tx * 2 + j;
            C[(size_t)rg * FF + cg] = (c[i][j].f2.x + c[i][j].f2.y) * s;
        }
    }
}

// GEMM2: h2 += (sum of h1 partials) @ W2^T, K chunk = 3072/16 = 192
// grid (768/32=24, 128/64=2, SPLIT2=16)
__global__ __launch_bounds__(256, 4) void gemm2_kernel(const float* __restrict__ W2) {
    U64 c[4][2];
    #pragma unroll
    for (int i = 0; i < 4; i++)
        #pragma unroll
        for (int j = 0; j < 2; j++) c[i][j].f2 = make_float2(0.f, 0.f);

    int m0 = blockIdx.y * 64, n0 = blockIdx.x * 32, kz = blockIdx.z;
    gemm_core<SPLIT1>(g_h1p, W2, FF, FF, m0, n0, kz * (FF / SPLIT2),
                      (FF / SPLIT2) / 32, (size_t)NSEQ * FF, c);

    int tx = threadIdx.x & 15, ty = threadIdx.x >> 4;
    #pragma unroll
    for (int i = 0; i < 4; i++) {
        int rg = m0 + ty * 4 + i;
        #pragma unroll
        for (int j = 0; j < 2; j++) {
            int cg = n0 + tx * 2 + j;
            atomicAdd(&g_h2[(size_t)rg * HIDDEN + cg], c[i][j].f2.x + c[i][j].f2.y);
        }
    }
}

// ---------------- L2 normalize rows ----------------
__global__ __launch_bounds__(256) void norm_kernel(float* __restrict__ out) {
    int s = blockIdx.x, tid = threadIdx.x;
    const float* row = &g_h2[s * HIDDEN];
    float ss = 0.f;
    for (int i = tid; i < HIDDEN; i += 256) { float v = row[i]; ss += v * v; }

    __shared__ float red[8];
    #pragma unroll
    for (int o = 16; o > 0; o >>= 1) ss += __shfl_xor_sync(0xffffffffu, ss, o);
    if ((tid & 31) == 0) red[tid >> 5] = ss;
    __syncthreads();
    __shared__ float sInv;
    if (tid == 0) {
        float tot = 0.f;
        #pragma unroll
        for (int w = 0; w < 8; w++) tot += red[w];
        sInv = 1.0f / fmaxf(sqrtf(tot), 1e-12f);
    }
    __syncthreads();
    float inv = sInv;
    for (int i = tid; i < HIDDEN; i += 256) out[s * HIDDEN + i] = row[i] * inv;
}

// ---------------- launch ----------------
extern "C" void kernel_launch(void* const* d_in, const int* in_sizes, int n_in,
                              void* d_out, int out_size) {
    const float* hs   = (const float*)d_in[0];   // [65536, 768] fp32
    const int*   lens = (const int*)  d_in[1];   // [128] int32
    const float* W1   = (const float*)d_in[2];   // [3072, 768] fp32
    const float* W2   = (const float*)d_in[3];   // [768, 3072] fp32
    float* out = (float*)d_out;                  // [128, 768] fp32

    zero_kernel<<<(NSEQ * HIDDEN + 255) / 256, 256>>>(lens);
    pool_kernel<<<TOKENS / TOKB, 192>>>(hs, lens);
    gemm1_kernel<<<dim3(FF / 32, NSEQ / 64, SPLIT1), 256>>>(W1);
    gemm2_kernel<<<dim3(HIDDEN / 32, NSEQ / 64, SPLIT2), 256>>>(W2);
    norm_kernel<<<NSEQ, 256>>>(out);
}

// round 3
// speedup vs baseline: 1.4272x; 1.1539x over previous
#include <cuda_runtime.h>

#define HIDDEN 768
#define FF     3072
#define NSEQ   128
#define TOKENS 65536
#define TOKB   32
#define SPLIT1 6      // gemm1 K-split: 768/6 = 128
#define SPLIT2 24     // gemm2 K-split: 3072/24 = 128
#define BK     16

// ---------------- scratch (device globals: no allocation) ----------------
__device__ float g_means[NSEQ * HIDDEN];            // pooled means (pool scales by 1/len)
__device__ float g_h1p[SPLIT1 * NSEQ * FF];         // gemm1 partials
__device__ float g_h1[NSEQ * FF];                   // reduced dense1 output
__device__ float g_h2p[SPLIT2 * NSEQ * HIDDEN];     // gemm2 partials

// ---------------- zero means ----------------
__global__ void zero_kernel() {
    int i = blockIdx.x * blockDim.x + threadIdx.x;
    if (i < NSEQ * HIDDEN) g_means[i] = 0.0f;
}

// ---------------- segment mean pooling (scaled atomics) ----------------
__global__ __launch_bounds__(192) void pool_kernel(const float* __restrict__ hs,
                                                   const int* __restrict__ lens) {
    __shared__ int sl[NSEQ];
    __shared__ int segof[TOKB];
    __shared__ float sinv[NSEQ];

    int tid = threadIdx.x;
    if (tid < NSEQ) {
        int l = lens[tid];
        sl[tid] = l;
        sinv[tid] = 1.0f / (float)l;
    }
    __syncthreads();
    #pragma unroll
    for (int off = 1; off < NSEQ; off <<= 1) {
        int v = 0;
        if (tid < NSEQ && tid >= off) v = sl[tid - off];
        __syncthreads();
        if (tid < NSEQ) sl[tid] += v;
        __syncthreads();
    }

    int t0 = blockIdx.x * TOKB;
    if (tid < TOKB) {
        int t = t0 + tid;
        int lo = 0, hi = NSEQ - 1;
        while (lo < hi) {
            int mid = (lo + hi) >> 1;
            if (sl[mid] > t) hi = mid; else lo = mid + 1;
        }
        segof[tid] = lo;
    }
    __syncthreads();

    const float4* h4 = (const float4*)hs;
    int col = tid;
    float4 acc = make_float4(0.f, 0.f, 0.f, 0.f);
    int cur = segof[0];

    #pragma unroll
    for (int i = 0; i < TOKB; i++) {
        float4 v = h4[(size_t)(t0 + i) * (HIDDEN / 4) + col];
        int s = segof[i];
        if (s != cur) {
            float inv = sinv[cur];
            float* dst = &g_means[cur * HIDDEN + col * 4];
            atomicAdd(dst + 0, acc.x * inv); atomicAdd(dst + 1, acc.y * inv);
            atomicAdd(dst + 2, acc.z * inv); atomicAdd(dst + 3, acc.w * inv);
            acc = make_float4(0.f, 0.f, 0.f, 0.f);
            cur = s;
        }
        acc.x += v.x; acc.y += v.y; acc.z += v.z; acc.w += v.w;
    }
    {
        float inv = sinv[cur];
        float* dst = &g_means[cur * HIDDEN + col * 4];
        atomicAdd(dst + 0, acc.x * inv); atomicAdd(dst + 1, acc.y * inv);
        atomicAdd(dst + 2, acc.z * inv); atomicAdd(dst + 3, acc.w * inv);
    }
}

// ---------------- packed f32x2 FMA ----------------
union U64 {
    float2 f2;
    unsigned long long u;
};

__device__ __forceinline__ void ffma2(U64& d, U64 a, U64 b) {
    asm("fma.rn.f32x2 %0, %1, %2, %0;" : "+l"(d.u) : "l"(a.u), "l"(b.u));
}

// ---- double-buffered NT GEMM core: block tile [128, 64], BK=16, micro 8x4 ----
// A: [128, ldA] K-contiguous; B: [N, ldB] K-contiguous. 256 threads (16x16).
__device__ __forceinline__ void gemm_core(
    const float* __restrict__ A, const float* __restrict__ B,
    int ldA, int ldB, int n0, int k0, int kIters, U64 (&c)[8][4])
{
    __shared__ float2 As[2][8][130];   // [buf][k2][m], padded
    __shared__ float2 Bs[2][8][66];    // [buf][k2][n], padded

    int tid = threadIdx.x;
    int q   = tid & 3;          // float4 index within 16-float K chunk
    int row = tid >> 2;         // 0..63

    const float* pa0 = A + (size_t)row * ldA + k0 + q * 4;
    const float* pa1 = pa0 + (size_t)64 * ldA;
    const float* pb  = B + (size_t)(n0 + row) * ldB + k0 + q * 4;

    float4 va0 = *(const float4*)pa0;
    float4 va1 = *(const float4*)pa1;
    float4 vb  = *(const float4*)pb;

    int tx = tid & 15, ty = tid >> 4;

    for (int kt = 0; kt < kIters; kt++) {
        int buf = kt & 1;
        As[buf][q * 2 + 0][row]      = make_float2(va0.x, va0.y);
        As[buf][q * 2 + 1][row]      = make_float2(va0.z, va0.w);
        As[buf][q * 2 + 0][row + 64] = make_float2(va1.x, va1.y);
        As[buf][q * 2 + 1][row + 64] = make_float2(va1.z, va1.w);
        Bs[buf][q * 2 + 0][row]      = make_float2(vb.x, vb.y);
        Bs[buf][q * 2 + 1][row]      = make_float2(vb.z, vb.w);
        __syncthreads();

        if (kt + 1 < kIters) {
            int off = (kt + 1) * BK;
            va0 = *(const float4*)(pa0 + off);
            va1 = *(const float4*)(pa1 + off);
            vb  = *(const float4*)(pb + off);
        }

        #pragma unroll
        for (int k2 = 0; k2 < 8; k2++) {
            U64 a[8], b[4];
            #pragma unroll
            for (int ii = 0; ii < 4; ii++) {
                float4 v = *(const float4*)(&As[buf][k2][ty * 8 + 2 * ii]);
                a[2 * ii + 0].f2 = make_float2(v.x, v.y);
                a[2 * ii + 1].f2 = make_float2(v.z, v.w);
            }
            #pragma unroll
            for (int jj = 0; jj < 2; jj++) {
                float4 v = *(const float4*)(&Bs[buf][k2][tx * 4 + 2 * jj]);
                b[2 * jj + 0].f2 = make_float2(v.x, v.y);
                b[2 * jj + 1].f2 = make_float2(v.z, v.w);
            }
            #pragma unroll
            for (int i = 0; i < 8; i++)
                #pragma unroll
                for (int j = 0; j < 4; j++)
                    ffma2(c[i][j], a[i], b[j]);
        }
        // single barrier per iter: double buffer makes the next write safe
    }
}

// GEMM1: h1p[kz] = means @ W1^T over K chunk 128. grid (48, SPLIT1)
__global__ __launch_bounds__(256, 2) void gemm1_kernel(const float* __restrict__ W1) {
    U64 c[8][4];
    #pragma unroll
    for (int i = 0; i < 8; i++)
        #pragma unroll
        for (int j = 0; j < 4; j++) c[i][j].f2 = make_float2(0.f, 0.f);

    int n0 = blockIdx.x * 64, kz = blockIdx.y;
    gemm_core(g_means, W1, HIDDEN, HIDDEN, n0, kz * (HIDDEN / SPLIT1),
              (HIDDEN / SPLIT1) / BK, c);

    float* C = g_h1p + (size_t)kz * NSEQ * FF;
    int tx = threadIdx.x & 15, ty = threadIdx.x >> 4;
    #pragma unroll
    for (int i = 0; i < 8; i++) {
        int m = ty * 8 + i;
        float4 v = make_float4(c[i][0].f2.x + c[i][0].f2.y,
                               c[i][1].f2.x + c[i][1].f2.y,
                               c[i][2].f2.x + c[i][2].f2.y,
                               c[i][3].f2.x + c[i][3].f2.y);
        *(float4*)&C[(size_t)m * FF + n0 + tx * 4] = v;
    }
}

// reduce gemm1 partials: g_h1 = sum over SPLIT1
__global__ __launch_bounds__(256) void reduce1_kernel() {
    int i = blockIdx.x * blockDim.x + threadIdx.x;   // float4 index
    const float4* p = (const float4*)g_h1p;
    float4 acc = p[i];
    #pragma unroll
    for (int s = 1; s < SPLIT1; s++) {
        float4 v = p[i + (size_t)s * (NSEQ * FF / 4)];
        acc.x += v.x; acc.y += v.y; acc.z += v.z; acc.w += v.w;
    }
    ((float4*)g_h1)[i] = acc;
}

// GEMM2: h2p[kz] = h1 @ W2^T over K chunk 128. grid (12, SPLIT2)
__global__ __launch_bounds__(256, 2) void gemm2_kernel(const float* __restrict__ W2) {
    U64 c[8][4];
    #pragma unroll
    for (int i = 0; i < 8; i++)
        #pragma unroll
        for (int j = 0; j < 4; j++) c[i][j].f2 = make_float2(0.f, 0.f);

    int n0 = blockIdx.x * 64, kz = blockIdx.y;
    gemm_core(g_h1, W2, FF, FF, n0, kz * (FF / SPLIT2),
              (FF / SPLIT2) / BK, c);

    float* C = g_h2p + (size_t)kz * NSEQ * HIDDEN;
    int tx = threadIdx.x & 15, ty = threadIdx.x >> 4;
    #pragma unroll
    for (int i = 0; i < 8; i++) {
        int m = ty * 8 + i;
        float4 v = make_float4(c[i][0].f2.x + c[i][0].f2.y,
                               c[i][1].f2.x + c[i][1].f2.y,
                               c[i][2].f2.x + c[i][2].f2.y,
                               c[i][3].f2.x + c[i][3].f2.y);
        *(float4*)&C[(size_t)m * HIDDEN + n0 + tx * 4] = v;
    }
}

// ---------------- reduce gemm2 partials + L2 normalize ----------------
__global__ __launch_bounds__(256) void norm_kernel(float* __restrict__ out) {
    int s = blockIdx.x, tid = threadIdx.x;
    float val[3];
    #pragma unroll
    for (int k = 0; k < 3; k++) {
        int col = tid + k * 256;
        float acc = 0.f;
        #pragma unroll
        for (int z = 0; z < SPLIT2; z++)
            acc += g_h2p[(size_t)z * NSEQ * HIDDEN + s * HIDDEN + col];
        val[k] = acc;
    }
    float ss = val[0] * val[0] + val[1] * val[1] + val[2] * val[2];

    __shared__ float red[8];
    #pragma unroll
    for (int o = 16; o > 0; o >>= 1) ss += __shfl_xor_sync(0xffffffffu, ss, o);
    if ((tid & 31) == 0) red[tid >> 5] = ss;
    __syncthreads();
    __shared__ float sInv;
    if (tid == 0) {
        float tot = 0.f;
        #pragma unroll
        for (int w = 0; w < 8; w++) tot += red[w];
        sInv = 1.0f / fmaxf(sqrtf(tot), 1e-12f);
    }
    __syncthreads();
    float inv = sInv;
    #pragma unroll
    for (int k = 0; k < 3; k++)
        out[s * HIDDEN + tid + k * 256] = val[k] * inv;
}

// ---------------- launch ----------------
extern "C" void kernel_launch(void* const* d_in, const int* in_sizes, int n_in,
                              void* d_out, int out_size) {
    const float* hs   = (const float*)d_in[0];   // [65536, 768] fp32
    const int*   lens = (const int*)  d_in[1];   // [128] int32
    const float* W1   = (const float*)d_in[2];   // [3072, 768] fp32
    const float* W2   = (const float*)d_in[3];   // [768, 3072] fp32
    float* out = (float*)d_out;                  // [128, 768] fp32

    zero_kernel<<<(NSEQ * HIDDEN + 255) / 256, 256>>>();
    pool_kernel<<<TOKENS / TOKB, 192>>>(hs, lens);
    gemm1_kernel<<<dim3(FF / 64, SPLIT1), 256>>>(W1);
    reduce1_kernel<<<(NSEQ * FF / 4) / 256, 256>>>();
    gemm2_kernel<<<dim3(HIDDEN / 64, SPLIT2), 256>>>(W2);
    norm_kernel<<<NSEQ, 256>>>(out);
}